// round 2
// baseline (speedup 1.0000x reference)
#include <cuda_runtime.h>
#include <math.h>

#define BN_SCALE 0.99999500003749972f

#define NB 8
#define NP 1024
#define NR (NB*NP)     // 8192 rows total
#define KNN 20

// ---------------- static scratch (no allocations allowed) ----------------
__device__ __align__(16) float g_dist[(size_t)NR * NP];   // 32MB; reused as h (8192x1024)
__device__ __align__(16) float g_cat [(size_t)NR * 512];  // x1|x2|x3|x4 concatenated
__device__ __align__(16) float g_Yn  [(size_t)NR * 256];
__device__ __align__(16) float g_Yc  [(size_t)NR * 256];
__device__ float g_xx[NR];
__device__ int   g_idx[NR * KNN];
__device__ float g_pmax[16 * NB * 1024];
__device__ float g_psum[16 * NB * 1024];
__device__ float g_f [NB * 2048];
__device__ float g_f1[NB * 512];
__device__ float g_f2[NB * 256];

// ---------------- row sum of squares ----------------
__global__ void __launch_bounds__(256) rowsum_kernel(
        const float* __restrict__ X, int ld, int C, float* __restrict__ xx) {
    int r = blockIdx.x * blockDim.x + threadIdx.x;
    if (r >= NR) return;
    const float* p = X + (size_t)r * ld;
    float s = 0.f;
    for (int c = 0; c < C; c++) s += p[c] * p[c];
    xx[r] = s;
}

// ---------------- generic NT GEMM: C = A(MxK) * B(NxK)^T, fused epilogues ----------------
// mode 0: plain   mode 1: dist (2*acc - xx[m] - xx[n])   mode 2: BN+ELU per column n
__global__ void __launch_bounds__(256) gemm_nt(int mode,
                        const float* __restrict__ A, int lda, int batA,
                        const float* __restrict__ B, int ldb, int batB,
                        float* __restrict__ C, int ldc, int batC, int K,
                        const float* __restrict__ xx, int batX,
                        const float* __restrict__ gg, const float* __restrict__ bb)
{
    A += (size_t)blockIdx.z * batA;
    B += (size_t)blockIdx.z * batB;
    C += (size_t)blockIdx.z * batC;
    const int m0 = blockIdx.y * 64;
    const int n0 = blockIdx.x * 64;
    __shared__ __align__(16) float As[16][64];
    __shared__ __align__(16) float Bs[16][64];
    const int tx = threadIdx.x, ty = threadIdx.y;
    const int t = ty * 16 + tx;
    const int lm = t >> 2;          // 0..63
    const int lk = (t & 3) * 4;     // 0,4,8,12
    float acc[4][4] = {};
    for (int k0 = 0; k0 < K; k0 += 16) {
        #pragma unroll
        for (int u = 0; u < 4; u++) {
            int kk = lk + u;
            As[kk][lm] = (k0 + kk < K) ? A[(size_t)(m0 + lm) * lda + k0 + kk] : 0.f;
            Bs[kk][lm] = (k0 + kk < K) ? B[(size_t)(n0 + lm) * ldb + k0 + kk] : 0.f;
        }
        __syncthreads();
        #pragma unroll
        for (int kk = 0; kk < 16; kk++) {
            float4 a4 = *reinterpret_cast<const float4*>(&As[kk][ty * 4]);
            float4 b4 = *reinterpret_cast<const float4*>(&Bs[kk][tx * 4]);
            float a[4] = {a4.x, a4.y, a4.z, a4.w};
            float b[4] = {b4.x, b4.y, b4.z, b4.w};
            #pragma unroll
            for (int i = 0; i < 4; i++)
                #pragma unroll
                for (int j = 0; j < 4; j++)
                    acc[i][j] = fmaf(a[i], b[j], acc[i][j]);
        }
        __syncthreads();
    }
    #pragma unroll
    for (int i = 0; i < 4; i++) {
        int m = m0 + ty * 4 + i;
        int n = n0 + tx * 4;
        float4 v;
        float* vp = &v.x;
        if (mode == 0) {
            #pragma unroll
            for (int j = 0; j < 4; j++) vp[j] = acc[i][j];
        } else if (mode == 1) {
            float xm = xx[batX * blockIdx.z + m];
            #pragma unroll
            for (int j = 0; j < 4; j++)
                vp[j] = 2.f * acc[i][j] - xm - xx[batX * blockIdx.z + n + j];
        } else {
            #pragma unroll
            for (int j = 0; j < 4; j++) {
                float s = gg[n + j] * BN_SCALE;
                float h = fmaf(s, acc[i][j], bb[n + j]);
                vp[j] = (h > 0.f) ? h : expm1f(h);
            }
        }
        *reinterpret_cast<float4*>(&C[(size_t)m * ldc + n]) = v;
    }
}

// ---------------- top-k (k=20) per row of 1024, lax.top_k tie semantics ----------------
__global__ void __launch_bounds__(256) topk_kernel(
        const float* __restrict__ D, int* __restrict__ out) {
    int warp = (blockIdx.x * blockDim.x + threadIdx.x) >> 5;
    int lane = threadIdx.x & 31;
    const float* row = D + (size_t)warp * NP;
    float v[32];
    #pragma unroll
    for (int j = 0; j < 32; j++) v[j] = row[lane + j * 32];
    int base = warp & ~(NP - 1);   // batch base as global row
    float lastV = INFINITY; int lastI = -1;
    for (int it = 0; it < KNN; it++) {
        float bv = -INFINITY; int bi = 1 << 30;
        #pragma unroll
        for (int j = 0; j < 32; j++) {
            int idx = lane + j * 32;
            float x = v[j];
            bool ok = (x < lastV) || (x == lastV && idx > lastI);
            if (ok && (x > bv || (x == bv && idx < bi))) { bv = x; bi = idx; }
        }
        #pragma unroll
        for (int off = 16; off; off >>= 1) {
            float ov = __shfl_xor_sync(0xffffffffu, bv, off);
            int   oi = __shfl_xor_sync(0xffffffffu, bi, off);
            if (ov > bv || (ov == bv && oi < bi)) { bv = ov; bi = oi; }
        }
        lastV = bv; lastI = bi;
        if (lane == 0) out[warp * KNN + it] = base + bi;
    }
}

// ---------------- edge-conv aggregation: gather 20 rows of Yn, max/min, BN+ELU ----------------
__global__ void __launch_bounds__(256) aggregate_kernel(
        const float* __restrict__ Yn, const float* __restrict__ Yc,
        int C, const int* __restrict__ idx,
        const float* __restrict__ gg, const float* __restrict__ bb,
        float* __restrict__ outp /* = g_cat + off, ld 512 */) {
    int r = blockIdx.x;
    int c = threadIdx.x;
    __shared__ int sidx[KNN];
    if (c < KNN) sidx[c] = idx[r * KNN + c];
    __syncthreads();
    float vmax = -INFINITY, vmin = INFINITY;
    #pragma unroll 4
    for (int j = 0; j < KNN; j++) {
        float v = Yn[(size_t)sidx[j] * C + c];
        vmax = fmaxf(vmax, v);
        vmin = fminf(vmin, v);
    }
    float center = Yc[(size_t)r * C + c] - Yn[(size_t)r * C + c];
    float s = gg[c] * BN_SCALE;
    float h = s * ((s >= 0.f ? vmax : vmin) + center) + bb[c];
    outp[(size_t)r * 512 + c] = (h > 0.f) ? h : expm1f(h);
}

// ---------------- global max/mean pooling over N (partial + combine) ----------------
__global__ void __launch_bounds__(256) pool_partial(
        const float* __restrict__ h,
        float* __restrict__ pmax, float* __restrict__ psum) {
    int o  = blockIdx.y * 256 + threadIdx.x;  // 0..1023
    int b  = blockIdx.x;                      // 0..7
    int nz = blockIdx.z;                      // 0..15
    float m = -INFINITY, s = 0.f;
    for (int n = nz * 64; n < nz * 64 + 64; n++) {
        float v = h[((size_t)(b * NP + n)) * 1024 + o];
        m = fmaxf(m, v); s += v;
    }
    pmax[(nz * NB + b) * 1024 + o] = m;
    psum[(nz * NB + b) * 1024 + o] = s;
}

__global__ void __launch_bounds__(256) pool_combine(
        const float* __restrict__ pmax, const float* __restrict__ psum,
        float* __restrict__ f) {
    int t = blockIdx.x * 256 + threadIdx.x;
    if (t >= NB * 1024) return;
    int b = t >> 10, o = t & 1023;
    float m = -INFINITY, s = 0.f;
    for (int c = 0; c < 16; c++) {
        m = fmaxf(m, pmax[(c * NB + b) * 1024 + o]);
        s += psum[(c * NB + b) * 1024 + o];
    }
    f[b * 2048 + o] = m;
    f[b * 2048 + 1024 + o] = s * (1.f / 1024.f);
}

// ---------------- tiny MLP: one warp per output element ----------------
__global__ void __launch_bounds__(256) mlp_kernel(
        const float* __restrict__ in, int Kd,
        const float* __restrict__ W,
        const float* __restrict__ gg, const float* __restrict__ bb,
        float* __restrict__ out, int Nout, int rows, int bnelu) {
    int wid  = (blockIdx.x * blockDim.x + threadIdx.x) >> 5;
    int lane = threadIdx.x & 31;
    if (wid >= rows * Nout) return;
    int r = wid / Nout, o = wid % Nout;
    const float* a = in + (size_t)r * Kd;
    const float* w = W  + (size_t)o * Kd;
    float s = 0.f;
    for (int k = lane; k < Kd; k += 32) s += a[k] * w[k];
    #pragma unroll
    for (int off = 16; off; off >>= 1) s += __shfl_xor_sync(0xffffffffu, s, off);
    if (lane == 0) {
        float v;
        if (bnelu) {
            float sc = gg[o] * BN_SCALE;
            v = fmaf(sc, s, bb[o]);
            v = (v > 0.f) ? v : expm1f(v);
        } else {
            v = s + bb[o];
        }
        out[(size_t)r * Nout + o] = v;
    }
}

// ---------------- host driver ----------------
static void edge_conv(const float* X, int ldx, int Cin,
                      const float* W, const float* g, const float* b,
                      int Cout, int catOff,
                      float* dist, float* xx, int* idx,
                      float* Yn, float* Yc, float* cat)
{
    dim3 blk(16, 16);
    rowsum_kernel<<<NR / 256, 256>>>(X, ldx, Cin, xx);
    gemm_nt<<<dim3(NP / 64, NP / 64, NB), blk>>>(1, X, ldx, NP * ldx, X, ldx, NP * ldx,
                                                 dist, NP, NP * NP, Cin,
                                                 xx, NP, nullptr, nullptr);
    topk_kernel<<<NR / 8, 256>>>(dist, idx);
    gemm_nt<<<dim3(Cout / 64, NR / 64, 1), blk>>>(0, X, ldx, 0, W, 2 * Cin, 0,
                                                  Yn, Cout, 0, Cin, nullptr, 0, nullptr, nullptr);
    gemm_nt<<<dim3(Cout / 64, NR / 64, 1), blk>>>(0, X, ldx, 0, W + Cin, 2 * Cin, 0,
                                                  Yc, Cout, 0, Cin, nullptr, 0, nullptr, nullptr);
    aggregate_kernel<<<NR, Cout>>>(Yn, Yc, Cout, idx, g, b, cat + catOff);
}

extern "C" void kernel_launch(void* const* d_in, const int* in_sizes, int n_in,
                              void* d_out, int out_size) {
    const float* x   = (const float*)d_in[0];
    const float* W1  = (const float*)d_in[1];
    const float* g1  = (const float*)d_in[2];
    const float* b1  = (const float*)d_in[3];
    const float* W2  = (const float*)d_in[4];
    const float* g2  = (const float*)d_in[5];
    const float* b2  = (const float*)d_in[6];
    const float* W3  = (const float*)d_in[7];
    const float* g3  = (const float*)d_in[8];
    const float* b3  = (const float*)d_in[9];
    const float* W4  = (const float*)d_in[10];
    const float* g4  = (const float*)d_in[11];
    const float* b4  = (const float*)d_in[12];
    const float* W5  = (const float*)d_in[13];
    const float* g5  = (const float*)d_in[14];
    const float* b5  = (const float*)d_in[15];
    const float* Wl1 = (const float*)d_in[16];
    const float* gl1 = (const float*)d_in[17];
    const float* bl1 = (const float*)d_in[18];
    const float* Wl2 = (const float*)d_in[19];
    const float* gl2 = (const float*)d_in[20];
    const float* bl2 = (const float*)d_in[21];
    const float* Wl3 = (const float*)d_in[22];
    const float* bl3 = (const float*)d_in[23];
    // d_in[24] = k (always 20)

    float *dist, *cat, *Yn, *Yc, *xx, *pmax, *psum, *f, *f1, *f2;
    int* idx;
    cudaGetSymbolAddress((void**)&dist, g_dist);
    cudaGetSymbolAddress((void**)&cat,  g_cat);
    cudaGetSymbolAddress((void**)&Yn,   g_Yn);
    cudaGetSymbolAddress((void**)&Yc,   g_Yc);
    cudaGetSymbolAddress((void**)&xx,   g_xx);
    cudaGetSymbolAddress((void**)&idx,  g_idx);
    cudaGetSymbolAddress((void**)&pmax, g_pmax);
    cudaGetSymbolAddress((void**)&psum, g_psum);
    cudaGetSymbolAddress((void**)&f,    g_f);
    cudaGetSymbolAddress((void**)&f1,   g_f1);
    cudaGetSymbolAddress((void**)&f2,   g_f2);

    // 4 edge-conv layers; outputs concatenated into cat[8192][512]
    edge_conv(x,         3,   3,   W1, g1, b1,  64,   0, dist, xx, idx, Yn, Yc, cat);
    edge_conv(cat + 0,   512, 64,  W2, g2, b2,  64,  64, dist, xx, idx, Yn, Yc, cat);
    edge_conv(cat + 64,  512, 64,  W3, g3, b3, 128, 128, dist, xx, idx, Yn, Yc, cat);
    edge_conv(cat + 128, 512, 128, W4, g4, b4, 256, 256, dist, xx, idx, Yn, Yc, cat);

    // conv5: h = elu(bn(cat @ W5^T))  (8192 x 1024), reuse dist buffer as h
    dim3 blk(16, 16);
    gemm_nt<<<dim3(1024 / 64, NR / 64, 1), blk>>>(2, cat, 512, 0, W5, 512, 0,
                                                  dist, 1024, 0, 512,
                                                  nullptr, 0, g5, b5);
    // global max + mean pooling -> f (8 x 2048)
    pool_partial<<<dim3(NB, 4, 16), 256>>>(dist, pmax, psum);
    pool_combine<<<32, 256>>>(pmax, psum, f);

    // MLP head
    mlp_kernel<<<512, 256>>>(f,  2048, Wl1, gl1, bl1, f1, 512, NB, 1);
    mlp_kernel<<<256, 256>>>(f1, 512,  Wl2, gl2, bl2, f2, 256, NB, 1);
    mlp_kernel<<<40,  256>>>(f2, 256,  Wl3, nullptr, bl3, (float*)d_out, 40, NB, 0);
}

// round 4
// speedup vs baseline: 1.2735x; 1.2735x over previous
#include <cuda_runtime.h>
#include <math.h>

#define BN_SCALE 0.99999500003749972f

#define NB 8
#define NP 1024
#define NR (NB*NP)     // 8192 rows total
#define KNN 20

// ---------------- static scratch (no allocations allowed) ----------------
__device__ __align__(16) float g_dist[(size_t)NR * NP];   // 32MB; reused as h (8192x1024)
__device__ __align__(16) float g_cat [(size_t)NR * 512];  // x1|x2|x3|x4 concatenated
__device__ __align__(16) float g_Yn  [(size_t)NR * 256];
__device__ __align__(16) float g_Yc  [(size_t)NR * 256];
__device__ float g_xx[NR];
__device__ int   g_idx[NR * KNN];
__device__ float g_pmax[16 * NB * 1024];
__device__ float g_psum[16 * NB * 1024];
__device__ float g_f [NB * 2048];
__device__ float g_f1[NB * 512];
__device__ float g_f2[NB * 256];

// ---------------- row sum of squares ----------------
__global__ void __launch_bounds__(256) rowsum_kernel(
        const float* __restrict__ X, int ld, int C, float* __restrict__ xx) {
    int r = blockIdx.x * blockDim.x + threadIdx.x;
    if (r >= NR) return;
    const float* p = X + (size_t)r * ld;
    float s = 0.f;
    for (int c = 0; c < C; c++) s += p[c] * p[c];
    xx[r] = s;
}

// ---------------- fp32 NT GEMM (used only for tiny K=3 layer-1 GEMMs) ----------------
// mode 0: plain   mode 1: dist (2*acc - xx[m] - xx[n])   mode 2: BN+ELU per column n
__global__ void __launch_bounds__(256) gemm_nt(int mode,
                        const float* __restrict__ A, int lda, int batA,
                        const float* __restrict__ B, int ldb, int batB,
                        float* __restrict__ C, int ldc, int batC, int K,
                        const float* __restrict__ xx, int batX,
                        const float* __restrict__ gg, const float* __restrict__ bb)
{
    A += (size_t)blockIdx.z * batA;
    B += (size_t)blockIdx.z * batB;
    C += (size_t)blockIdx.z * batC;
    const int m0 = blockIdx.y * 64;
    const int n0 = blockIdx.x * 64;
    __shared__ __align__(16) float As[16][64];
    __shared__ __align__(16) float Bs[16][64];
    const int tx = threadIdx.x, ty = threadIdx.y;
    const int t = ty * 16 + tx;
    const int lm = t >> 2;          // 0..63
    const int lk = (t & 3) * 4;     // 0,4,8,12
    float acc[4][4] = {};
    for (int k0 = 0; k0 < K; k0 += 16) {
        #pragma unroll
        for (int u = 0; u < 4; u++) {
            int kk = lk + u;
            As[kk][lm] = (k0 + kk < K) ? A[(size_t)(m0 + lm) * lda + k0 + kk] : 0.f;
            Bs[kk][lm] = (k0 + kk < K) ? B[(size_t)(n0 + lm) * ldb + k0 + kk] : 0.f;
        }
        __syncthreads();
        #pragma unroll
        for (int kk = 0; kk < 16; kk++) {
            float4 a4 = *reinterpret_cast<const float4*>(&As[kk][ty * 4]);
            float4 b4 = *reinterpret_cast<const float4*>(&Bs[kk][tx * 4]);
            float a[4] = {a4.x, a4.y, a4.z, a4.w};
            float b[4] = {b4.x, b4.y, b4.z, b4.w};
            #pragma unroll
            for (int i = 0; i < 4; i++)
                #pragma unroll
                for (int j = 0; j < 4; j++)
                    acc[i][j] = fmaf(a[i], b[j], acc[i][j]);
        }
        __syncthreads();
    }
    #pragma unroll
    for (int i = 0; i < 4; i++) {
        int m = m0 + ty * 4 + i;
        int n = n0 + tx * 4;
        float4 v;
        float* vp = &v.x;
        if (mode == 0) {
            #pragma unroll
            for (int j = 0; j < 4; j++) vp[j] = acc[i][j];
        } else if (mode == 1) {
            float xm = xx[batX * blockIdx.z + m];
            #pragma unroll
            for (int j = 0; j < 4; j++)
                vp[j] = 2.f * acc[i][j] - xm - xx[batX * blockIdx.z + n + j];
        } else {
            #pragma unroll
            for (int j = 0; j < 4; j++) {
                float s = gg[n + j] * BN_SCALE;
                float h = fmaf(s, acc[i][j], bb[n + j]);
                vp[j] = (h > 0.f) ? h : expm1f(h);
            }
        }
        *reinterpret_cast<float4*>(&C[(size_t)m * ldc + n]) = v;
    }
}

// ---------------- split-tf32 tensor-core NT GEMM (3xTF32, ~fp32 accuracy) ----------------
// C(MxN) = A(MxK,row) * B(NxK,row)^T ; requires K%16==0, M%128==0.
// Block 128x128, 8 warps in 2(m) x 4(n), warp tile 64x32, mma m16n8k8.
__device__ __forceinline__ unsigned f2tf(float f) {
    unsigned u; asm("cvt.rna.tf32.f32 %0, %1;" : "=r"(u) : "f"(f)); return u;
}
__device__ __forceinline__ void split_store(unsigned* hi, unsigned* lo, float4 v) {
    unsigned hx = f2tf(v.x), hy = f2tf(v.y), hz = f2tf(v.z), hw = f2tf(v.w);
    uint4 H = {hx, hy, hz, hw};
    uint4 L = {f2tf(v.x - __uint_as_float(hx)), f2tf(v.y - __uint_as_float(hy)),
               f2tf(v.z - __uint_as_float(hz)), f2tf(v.w - __uint_as_float(hw))};
    *(uint4*)hi = H;
    *(uint4*)lo = L;
}
#define MMA_TF32(c, a0,a1,a2,a3, b0,b1)                                        \
    asm volatile("mma.sync.aligned.m16n8k8.row.col.f32.tf32.tf32.f32 "          \
                 "{%0,%1,%2,%3}, {%4,%5,%6,%7}, {%8,%9}, {%0,%1,%2,%3};"        \
                 : "+f"(c[0]), "+f"(c[1]), "+f"(c[2]), "+f"(c[3])               \
                 : "r"(a0), "r"(a1), "r"(a2), "r"(a3), "r"(b0), "r"(b1))

__global__ void __launch_bounds__(256) gemm_tf32(int mode, int N,
        const float* __restrict__ A, int lda, int batA,
        const float* __restrict__ B, int ldb, int batB,
        float* __restrict__ C, int ldc, int batC, int K,
        const float* __restrict__ xx, int batX,
        const float* __restrict__ gg, const float* __restrict__ bb)
{
    A += (size_t)blockIdx.z * batA;
    B += (size_t)blockIdx.z * batB;
    C += (size_t)blockIdx.z * batC;
    const float* xb = xx ? (xx + (size_t)batX * blockIdx.z) : xx;

    const int m0 = blockIdx.y * 128;
    const int n0 = blockIdx.x * 128;

    // hi/lo tiles, stride 20 -> conflict-free fragment loads. 40KB total.
    __shared__ unsigned Ah[128][20], Al[128][20];
    __shared__ unsigned Bh[128][20], Bl[128][20];

    const int tid = threadIdx.x;
    const int w  = tid >> 5, l = tid & 31;
    const int g  = l >> 2,  t4 = l & 3;
    const int wm = (w & 1) * 64;
    const int wn = (w >> 1) * 32;
    const int lr = tid >> 2;          // 0..63
    const int lk = (tid & 3) * 4;     // 0,4,8,12

    float c[4][4][4];
    #pragma unroll
    for (int i = 0; i < 4; i++)
        #pragma unroll
        for (int j = 0; j < 4; j++)
            #pragma unroll
            for (int q = 0; q < 4; q++) c[i][j][q] = 0.f;

    const float4 z4 = {0.f, 0.f, 0.f, 0.f};
    float4 ra0, ra1, rb0, rb1;

    // prologue: load k-tile 0 into registers
    {
        const float* Ap = A + (size_t)(m0 + lr) * lda + lk;
        ra0 = *(const float4*)Ap;
        ra1 = *(const float4*)(Ap + (size_t)64 * lda);
        int nr0 = n0 + lr, nr1 = n0 + lr + 64;
        rb0 = (nr0 < N) ? *(const float4*)(B + (size_t)nr0 * ldb + lk) : z4;
        rb1 = (nr1 < N) ? *(const float4*)(B + (size_t)nr1 * ldb + lk) : z4;
    }

    const int T = K / 16;
    for (int t = 0; t < T; t++) {
        __syncthreads();   // previous tile's mma done reading smem
        split_store(&Ah[lr][lk],      &Al[lr][lk],      ra0);
        split_store(&Ah[lr + 64][lk], &Al[lr + 64][lk], ra1);
        split_store(&Bh[lr][lk],      &Bl[lr][lk],      rb0);
        split_store(&Bh[lr + 64][lk], &Bl[lr + 64][lk], rb1);
        __syncthreads();
        if (t + 1 < T) {   // prefetch next tile, overlapped with mma below
            int k0 = (t + 1) * 16;
            const float* Ap = A + (size_t)(m0 + lr) * lda + k0 + lk;
            ra0 = *(const float4*)Ap;
            ra1 = *(const float4*)(Ap + (size_t)64 * lda);
            int nr0 = n0 + lr, nr1 = n0 + lr + 64;
            rb0 = (nr0 < N) ? *(const float4*)(B + (size_t)nr0 * ldb + k0 + lk) : z4;
            rb1 = (nr1 < N) ? *(const float4*)(B + (size_t)nr1 * ldb + k0 + lk) : z4;
        }
        #pragma unroll
        for (int kk = 0; kk < 16; kk += 8) {
            unsigned ah[4][4], al[4][4], bh[4][2], bl[4][2];
            #pragma unroll
            for (int mi = 0; mi < 4; mi++) {
                int r = wm + mi * 16 + g;
                ah[mi][0] = Ah[r    ][kk + t4];
                ah[mi][1] = Ah[r + 8][kk + t4];
                ah[mi][2] = Ah[r    ][kk + t4 + 4];
                ah[mi][3] = Ah[r + 8][kk + t4 + 4];
                al[mi][0] = Al[r    ][kk + t4];
                al[mi][1] = Al[r + 8][kk + t4];
                al[mi][2] = Al[r    ][kk + t4 + 4];
                al[mi][3] = Al[r + 8][kk + t4 + 4];
            }
            #pragma unroll
            for (int ni = 0; ni < 4; ni++) {
                int r = wn + ni * 8 + g;
                bh[ni][0] = Bh[r][kk + t4];
                bh[ni][1] = Bh[r][kk + t4 + 4];
                bl[ni][0] = Bl[r][kk + t4];
                bl[ni][1] = Bl[r][kk + t4 + 4];
            }
            #pragma unroll
            for (int mi = 0; mi < 4; mi++)
                #pragma unroll
                for (int ni = 0; ni < 4; ni++) {
                    float* cc = c[mi][ni];
                    MMA_TF32(cc, ah[mi][0], ah[mi][1], ah[mi][2], ah[mi][3],
                                 bl[ni][0], bl[ni][1]);
                    MMA_TF32(cc, al[mi][0], al[mi][1], al[mi][2], al[mi][3],
                                 bh[ni][0], bh[ni][1]);
                    MMA_TF32(cc, ah[mi][0], ah[mi][1], ah[mi][2], ah[mi][3],
                                 bh[ni][0], bh[ni][1]);
                }
        }
    }

    // ---- epilogue ----
    #pragma unroll
    for (int mi = 0; mi < 4; mi++) {
        int r0 = m0 + wm + mi * 16 + g;
        int r1 = r0 + 8;
        float xm0 = 0.f, xm1 = 0.f;
        if (mode == 1) { xm0 = xb[r0]; xm1 = xb[r1]; }
        #pragma unroll
        for (int ni = 0; ni < 4; ni++) {
            int n = n0 + wn + ni * 8 + t4 * 2;
            if (n < N) {
                float v0 = c[mi][ni][0], v1 = c[mi][ni][1];
                float v2 = c[mi][ni][2], v3 = c[mi][ni][3];
                if (mode == 1) {
                    float xn0 = xb[n], xn1 = xb[n + 1];
                    v0 = 2.f * v0 - xm0 - xn0;  v1 = 2.f * v1 - xm0 - xn1;
                    v2 = 2.f * v2 - xm1 - xn0;  v3 = 2.f * v3 - xm1 - xn1;
                } else if (mode == 2) {
                    float s0 = gg[n] * BN_SCALE, s1 = gg[n + 1] * BN_SCALE;
                    float b0v = bb[n], b1v = bb[n + 1];
                    v0 = fmaf(s0, v0, b0v); v0 = (v0 > 0.f) ? v0 : expm1f(v0);
                    v1 = fmaf(s1, v1, b1v); v1 = (v1 > 0.f) ? v1 : expm1f(v1);
                    v2 = fmaf(s0, v2, b0v); v2 = (v2 > 0.f) ? v2 : expm1f(v2);
                    v3 = fmaf(s1, v3, b1v); v3 = (v3 > 0.f) ? v3 : expm1f(v3);
                }
                float2 p0 = {v0, v1}, p1 = {v2, v3};
                *(float2*)&C[(size_t)r0 * ldc + n] = p0;
                *(float2*)&C[(size_t)r1 * ldc + n] = p1;
            }
        }
    }
}

// ---------------- top-k (k=20) per row of 1024, lax.top_k tie semantics ----------------
__global__ void __launch_bounds__(256) topk_kernel(
        const float* __restrict__ D, int* __restrict__ out) {
    int warp = (blockIdx.x * blockDim.x + threadIdx.x) >> 5;
    int lane = threadIdx.x & 31;
    const float* row = D + (size_t)warp * NP;
    float v[32];
    #pragma unroll
    for (int j = 0; j < 32; j++) v[j] = row[lane + j * 32];
    int base = warp & ~(NP - 1);   // batch base as global row
    float lastV = INFINITY; int lastI = -1;
    for (int it = 0; it < KNN; it++) {
        float bv = -INFINITY; int bi = 1 << 30;
        #pragma unroll
        for (int j = 0; j < 32; j++) {
            int idx = lane + j * 32;
            float x = v[j];
            bool ok = (x < lastV) || (x == lastV && idx > lastI);
            if (ok && (x > bv || (x == bv && idx < bi))) { bv = x; bi = idx; }
        }
        #pragma unroll
        for (int off = 16; off; off >>= 1) {
            float ov = __shfl_xor_sync(0xffffffffu, bv, off);
            int   oi = __shfl_xor_sync(0xffffffffu, bi, off);
            if (ov > bv || (ov == bv && oi < bi)) { bv = ov; bi = oi; }
        }
        lastV = bv; lastI = bi;
        if (lane == 0) out[warp * KNN + it] = base + bi;
    }
}

// ---------------- edge-conv aggregation: gather 20 rows of Yn, max/min, BN+ELU ----------------
__global__ void __launch_bounds__(256) aggregate_kernel(
        const float* __restrict__ Yn, const float* __restrict__ Yc,
        int C, const int* __restrict__ idx,
        const float* __restrict__ gg, const float* __restrict__ bb,
        float* __restrict__ outp /* = g_cat + off, ld 512 */) {
    int r = blockIdx.x;
    int c = threadIdx.x;
    __shared__ int sidx[KNN];
    if (c < KNN) sidx[c] = idx[r * KNN + c];
    __syncthreads();
    float vmax = -INFINITY, vmin = INFINITY;
    #pragma unroll 4
    for (int j = 0; j < KNN; j++) {
        float v = Yn[(size_t)sidx[j] * C + c];
        vmax = fmaxf(vmax, v);
        vmin = fminf(vmin, v);
    }
    float center = Yc[(size_t)r * C + c] - Yn[(size_t)r * C + c];
    float s = gg[c] * BN_SCALE;
    float h = s * ((s >= 0.f ? vmax : vmin) + center) + bb[c];
    outp[(size_t)r * 512 + c] = (h > 0.f) ? h : expm1f(h);
}

// ---------------- global max/mean pooling over N (partial + combine) ----------------
__global__ void __launch_bounds__(256) pool_partial(
        const float* __restrict__ h,
        float* __restrict__ pmax, float* __restrict__ psum) {
    int o  = blockIdx.y * 256 + threadIdx.x;  // 0..1023
    int b  = blockIdx.x;                      // 0..7
    int nz = blockIdx.z;                      // 0..15
    float m = -INFINITY, s = 0.f;
    for (int n = nz * 64; n < nz * 64 + 64; n++) {
        float v = h[((size_t)(b * NP + n)) * 1024 + o];
        m = fmaxf(m, v); s += v;
    }
    pmax[(nz * NB + b) * 1024 + o] = m;
    psum[(nz * NB + b) * 1024 + o] = s;
}

__global__ void __launch_bounds__(256) pool_combine(
        const float* __restrict__ pmax, const float* __restrict__ psum,
        float* __restrict__ f) {
    int t = blockIdx.x * 256 + threadIdx.x;
    if (t >= NB * 1024) return;
    int b = t >> 10, o = t & 1023;
    float m = -INFINITY, s = 0.f;
    for (int c = 0; c < 16; c++) {
        m = fmaxf(m, pmax[(c * NB + b) * 1024 + o]);
        s += psum[(c * NB + b) * 1024 + o];
    }
    f[b * 2048 + o] = m;
    f[b * 2048 + 1024 + o] = s * (1.f / 1024.f);
}

// ---------------- tiny MLP: one warp per output element ----------------
__global__ void __launch_bounds__(256) mlp_kernel(
        const float* __restrict__ in, int Kd,
        const float* __restrict__ W,
        const float* __restrict__ gg, const float* __restrict__ bb,
        float* __restrict__ out, int Nout, int rows, int bnelu) {
    int wid  = (blockIdx.x * blockDim.x + threadIdx.x) >> 5;
    int lane = threadIdx.x & 31;
    if (wid >= rows * Nout) return;
    int r = wid / Nout, o = wid % Nout;
    const float* a = in + (size_t)r * Kd;
    const float* w = W  + (size_t)o * Kd;
    float s = 0.f;
    for (int k = lane; k < Kd; k += 32) s += a[k] * w[k];
    #pragma unroll
    for (int off = 16; off; off >>= 1) s += __shfl_xor_sync(0xffffffffu, s, off);
    if (lane == 0) {
        float v;
        if (bnelu) {
            float sc = gg[o] * BN_SCALE;
            v = fmaf(sc, s, bb[o]);
            v = (v > 0.f) ? v : expm1f(v);
        } else {
            v = s + bb[o];
        }
        out[(size_t)r * Nout + o] = v;
    }
}

// ---------------- host driver ----------------
static void edge_conv(const float* X, int ldx, int Cin,
                      const float* W, const float* g, const float* b,
                      int Cout, int catOff, int use_tc,
                      float* dist, float* xx, int* idx,
                      float* Yn, float* Yc, float* cat)
{
    dim3 blk(16, 16);
    rowsum_kernel<<<NR / 256, 256>>>(X, ldx, Cin, xx);
    if (use_tc) {
        gemm_tf32<<<dim3(NP / 128, NP / 128, NB), 256>>>(1, NP,
            X, ldx, NP * ldx, X, ldx, NP * ldx,
            dist, NP, NP * NP, Cin, xx, NP, nullptr, nullptr);
    } else {
        gemm_nt<<<dim3(NP / 64, NP / 64, NB), blk>>>(1, X, ldx, NP * ldx, X, ldx, NP * ldx,
            dist, NP, NP * NP, Cin, xx, NP, nullptr, nullptr);
    }
    topk_kernel<<<NR / 8, 256>>>(dist, idx);
    if (use_tc) {
        int gx = (Cout + 127) / 128;
        gemm_tf32<<<dim3(gx, NR / 128, 1), 256>>>(0, Cout,
            X, ldx, 0, W, 2 * Cin, 0,
            Yn, Cout, 0, Cin, nullptr, 0, nullptr, nullptr);
        gemm_tf32<<<dim3(gx, NR / 128, 1), 256>>>(0, Cout,
            X, ldx, 0, W + Cin, 2 * Cin, 0,
            Yc, Cout, 0, Cin, nullptr, 0, nullptr, nullptr);
    } else {
        gemm_nt<<<dim3(Cout / 64, NR / 64, 1), blk>>>(0, X, ldx, 0, W, 2 * Cin, 0,
            Yn, Cout, 0, Cin, nullptr, 0, nullptr, nullptr);
        gemm_nt<<<dim3(Cout / 64, NR / 64, 1), blk>>>(0, X, ldx, 0, W + Cin, 2 * Cin, 0,
            Yc, Cout, 0, Cin, nullptr, 0, nullptr, nullptr);
    }
    aggregate_kernel<<<NR, Cout>>>(Yn, Yc, Cout, idx, g, b, cat + catOff);
}

extern "C" void kernel_launch(void* const* d_in, const int* in_sizes, int n_in,
                              void* d_out, int out_size) {
    const float* x   = (const float*)d_in[0];
    const float* W1  = (const float*)d_in[1];
    const float* g1  = (const float*)d_in[2];
    const float* b1  = (const float*)d_in[3];
    const float* W2  = (const float*)d_in[4];
    const float* g2  = (const float*)d_in[5];
    const float* b2  = (const float*)d_in[6];
    const float* W3  = (const float*)d_in[7];
    const float* g3  = (const float*)d_in[8];
    const float* b3  = (const float*)d_in[9];
    const float* W4  = (const float*)d_in[10];
    const float* g4  = (const float*)d_in[11];
    const float* b4  = (const float*)d_in[12];
    const float* W5  = (const float*)d_in[13];
    const float* g5  = (const float*)d_in[14];
    const float* b5  = (const float*)d_in[15];
    const float* Wl1 = (const float*)d_in[16];
    const float* gl1 = (const float*)d_in[17];
    const float* bl1 = (const float*)d_in[18];
    const float* Wl2 = (const float*)d_in[19];
    const float* gl2 = (const float*)d_in[20];
    const float* bl2 = (const float*)d_in[21];
    const float* Wl3 = (const float*)d_in[22];
    const float* bl3 = (const float*)d_in[23];
    // d_in[24] = k (always 20)

    float *dist, *cat, *Yn, *Yc, *xx, *pmax, *psum, *f, *f1, *f2;
    int* idx;
    cudaGetSymbolAddress((void**)&dist, g_dist);
    cudaGetSymbolAddress((void**)&cat,  g_cat);
    cudaGetSymbolAddress((void**)&Yn,   g_Yn);
    cudaGetSymbolAddress((void**)&Yc,   g_Yc);
    cudaGetSymbolAddress((void**)&xx,   g_xx);
    cudaGetSymbolAddress((void**)&idx,  g_idx);
    cudaGetSymbolAddress((void**)&pmax, g_pmax);
    cudaGetSymbolAddress((void**)&psum, g_psum);
    cudaGetSymbolAddress((void**)&f,    g_f);
    cudaGetSymbolAddress((void**)&f1,   g_f1);
    cudaGetSymbolAddress((void**)&f2,   g_f2);

    // 4 edge-conv layers; outputs concatenated into cat[8192][512]
    // layer 1 (K=3): exact fp32; layers 2-4: split-tf32 tensor cores (~fp32 accuracy)
    edge_conv(x,         3,   3,   W1, g1, b1,  64,   0, 0, dist, xx, idx, Yn, Yc, cat);
    edge_conv(cat + 0,   512, 64,  W2, g2, b2,  64,  64, 1, dist, xx, idx, Yn, Yc, cat);
    edge_conv(cat + 64,  512, 64,  W3, g3, b3, 128, 128, 1, dist, xx, idx, Yn, Yc, cat);
    edge_conv(cat + 128, 512, 128, W4, g4, b4, 256, 256, 1, dist, xx, idx, Yn, Yc, cat);

    // conv5: h = elu(bn(cat @ W5^T))  (8192 x 1024), reuse dist buffer as h
    gemm_tf32<<<dim3(1024 / 128, NR / 128, 1), 256>>>(2, 1024,
        cat, 512, 0, W5, 512, 0,
        dist, 1024, 0, 512, nullptr, 0, g5, b5);

    // global max + mean pooling -> f (8 x 2048)
    pool_partial<<<dim3(NB, 4, 16), 256>>>(dist, pmax, psum);
    pool_combine<<<32, 256>>>(pmax, psum, f);

    // MLP head
    mlp_kernel<<<512, 256>>>(f,  2048, Wl1, gl1, bl1, f1, 512, NB, 1);
    mlp_kernel<<<256, 256>>>(f1, 512,  Wl2, gl2, bl2, f2, 256, NB, 1);
    mlp_kernel<<<40,  256>>>(f2, 256,  Wl3, nullptr, bl3, (float*)d_out, 40, NB, 0);
}

// round 6
// speedup vs baseline: 1.4780x; 1.1605x over previous
#include <cuda_runtime.h>
#include <math.h>

#define BN_SCALE 0.99999500003749972f

#define NB 8
#define NP 1024
#define NR (NB*NP)     // 8192 rows total
#define KNN 20

// ---------------- static scratch (no allocations allowed) ----------------
__device__ __align__(16) float g_dist[(size_t)NR * NP];   // 32MB; reused as h (8192x1024)
__device__ __align__(16) float g_cat [(size_t)NR * 512];  // x1|x2|x3|x4 concatenated
__device__ __align__(16) float g_Y   [(size_t)2 * NR * 256];  // Yn | Yc (z-batched)
__device__ float g_xx[NR];
__device__ int   g_idx[NR * KNN];
__device__ float g_pmax[16 * NB * 1024];
__device__ float g_psum[16 * NB * 1024];
__device__ float g_f [NB * 2048];
__device__ float g_f1[NB * 512];
__device__ float g_f2[NB * 256];

// ---------------- row sum of squares (layer 1 only) ----------------
__global__ void __launch_bounds__(256) rowsum_kernel(
        const float* __restrict__ X, int ld, int C, float* __restrict__ xx) {
    int r = blockIdx.x * blockDim.x + threadIdx.x;
    if (r >= NR) return;
    const float* p = X + (size_t)r * ld;
    float s = 0.f;
    for (int c = 0; c < C; c++) s += p[c] * p[c];
    xx[r] = s;
}

// ---------------- fp32 NT GEMM (layer-1 K=3 only) ----------------
// mode 0: plain   mode 1: dist (2*acc - xx[m] - xx[n])
__global__ void __launch_bounds__(256) gemm_nt(int mode,
                        const float* __restrict__ A, int lda, int batA,
                        const float* __restrict__ B, int ldb, int batB,
                        float* __restrict__ C, int ldc, int batC, int K,
                        const float* __restrict__ xx, int batX)
{
    A += (size_t)blockIdx.z * batA;
    B += (size_t)blockIdx.z * batB;
    C += (size_t)blockIdx.z * batC;
    const int m0 = blockIdx.y * 64;
    const int n0 = blockIdx.x * 64;
    __shared__ __align__(16) float As[16][64];
    __shared__ __align__(16) float Bs[16][64];
    const int tx = threadIdx.x, ty = threadIdx.y;
    const int t = ty * 16 + tx;
    const int lm = t >> 2;
    const int lk = (t & 3) * 4;
    float acc[4][4] = {};
    for (int k0 = 0; k0 < K; k0 += 16) {
        #pragma unroll
        for (int u = 0; u < 4; u++) {
            int kk = lk + u;
            As[kk][lm] = (k0 + kk < K) ? A[(size_t)(m0 + lm) * lda + k0 + kk] : 0.f;
            Bs[kk][lm] = (k0 + kk < K) ? B[(size_t)(n0 + lm) * ldb + k0 + kk] : 0.f;
        }
        __syncthreads();
        #pragma unroll
        for (int kk = 0; kk < 16; kk++) {
            float4 a4 = *reinterpret_cast<const float4*>(&As[kk][ty * 4]);
            float4 b4 = *reinterpret_cast<const float4*>(&Bs[kk][tx * 4]);
            float a[4] = {a4.x, a4.y, a4.z, a4.w};
            float b[4] = {b4.x, b4.y, b4.z, b4.w};
            #pragma unroll
            for (int i = 0; i < 4; i++)
                #pragma unroll
                for (int j = 0; j < 4; j++)
                    acc[i][j] = fmaf(a[i], b[j], acc[i][j]);
        }
        __syncthreads();
    }
    #pragma unroll
    for (int i = 0; i < 4; i++) {
        int m = m0 + ty * 4 + i;
        int n = n0 + tx * 4;
        float4 v; float* vp = &v.x;
        if (mode == 1) {
            float xm = xx[batX * blockIdx.z + m];
            #pragma unroll
            for (int j = 0; j < 4; j++)
                vp[j] = 2.f * acc[i][j] - xm - xx[batX * blockIdx.z + n + j];
        } else {
            #pragma unroll
            for (int j = 0; j < 4; j++) vp[j] = acc[i][j];
        }
        *reinterpret_cast<float4*>(&C[(size_t)m * ldc + n]) = v;
    }
}

// ---------------- split-tf32 tensor-core NT GEMM (3xTF32, ~fp32 accuracy) ----------------
// C(MxN) = A(MxK,row) * B(NxK,row)^T ; K%16==0, M%128==0.
// Block 128x128, 8 warps 2(m)x4(n), warp tile 64x32, mma m16n8k8.
// fp32 tiles in smem (double-buffered, cp.async), split to hi/lo at frag load.
// sym=1 (with mode 1): compute lower triangle only, mirror via smem transpose.
__device__ __forceinline__ unsigned f2tf(float f) {
    unsigned u; asm("cvt.rna.tf32.f32 %0, %1;" : "=r"(u) : "f"(f)); return u;
}
__device__ __forceinline__ void spl(float f, unsigned& hi, unsigned& lo) {
    hi = f2tf(f);
    lo = f2tf(f - __uint_as_float(hi));
}
__device__ __forceinline__ void cp16(void* dst, const void* src, int sz) {
    unsigned d = (unsigned)__cvta_generic_to_shared(dst);
    asm volatile("cp.async.ca.shared.global [%0], [%1], 16, %2;"
                 :: "r"(d), "l"(src), "r"(sz));
}
#define MMA_TF32(c, a0,a1,a2,a3, b0,b1)                                        \
    asm volatile("mma.sync.aligned.m16n8k8.row.col.f32.tf32.tf32.f32 "          \
                 "{%0,%1,%2,%3}, {%4,%5,%6,%7}, {%8,%9}, {%0,%1,%2,%3};"        \
                 : "+f"(c[0]), "+f"(c[1]), "+f"(c[2]), "+f"(c[3])               \
                 : "r"(a0), "r"(a1), "r"(a2), "r"(a3), "r"(b0), "r"(b1))

__global__ void __launch_bounds__(256) gemm_tf32(int mode, int N, int sym,
        const float* __restrict__ A, int lda, int batA,
        const float* __restrict__ B, int ldb, int batB,
        float* __restrict__ C, int ldc, int batC, int K,
        const float* __restrict__ xx, int batX,
        const float* __restrict__ gg, const float* __restrict__ bb)
{
    if (sym && blockIdx.x > blockIdx.y) return;   // lower triangle only
    A += (size_t)blockIdx.z * batA;
    B += (size_t)blockIdx.z * batB;
    C += (size_t)blockIdx.z * batC;
    const float* xb = xx ? (xx + (size_t)batX * blockIdx.z) : xx;

    const int m0 = blockIdx.y * 128;
    const int n0 = blockIdx.x * 128;

    __shared__ __align__(16) float As[2][128][20];   // fp32 tiles, 20KB
    __shared__ __align__(16) float Bs[2][128][20];   // 20KB

    const int tid = threadIdx.x;
    const int w  = tid >> 5, l = tid & 31;
    const int g  = l >> 2,  t4 = l & 3;
    const int wm = (w & 1) * 64;
    const int wn = (w >> 1) * 32;
    const int lr = tid >> 2;          // 0..63
    const int lk = (tid & 3) * 4;     // 0,4,8,12

    float c[4][4][4];
    #pragma unroll
    for (int i = 0; i < 4; i++)
        #pragma unroll
        for (int j = 0; j < 4; j++)
            #pragma unroll
            for (int q = 0; q < 4; q++) c[i][j][q] = 0.f;

    #define LOAD_TILE(buf, k0)                                                  \
    {                                                                           \
        const float* Ap = A + (size_t)(m0 + lr) * lda + (k0) + lk;              \
        cp16(&As[buf][lr][lk],      Ap, 16);                                    \
        cp16(&As[buf][lr + 64][lk], Ap + (size_t)64 * lda, 16);                 \
        int nr0 = n0 + lr, nr1 = nr0 + 64;                                      \
        int cr0 = nr0 < N ? nr0 : N - 1, cr1 = nr1 < N ? nr1 : N - 1;           \
        cp16(&Bs[buf][lr][lk],      B + (size_t)cr0 * ldb + (k0) + lk,          \
             nr0 < N ? 16 : 0);                                                 \
        cp16(&Bs[buf][lr + 64][lk], B + (size_t)cr1 * ldb + (k0) + lk,          \
             nr1 < N ? 16 : 0);                                                 \
        asm volatile("cp.async.commit_group;");                                 \
    }

    LOAD_TILE(0, 0);
    asm volatile("cp.async.wait_group 0;" ::: "memory");
    __syncthreads();

    const int T = K / 16;
    int p = 0;
    for (int t = 0; t < T; t++) {
        if (t + 1 < T) LOAD_TILE(p ^ 1, (t + 1) * 16);
        #pragma unroll
        for (int kk = 0; kk < 16; kk += 8) {
            unsigned ah[4][4], al[4][4], bh[4][2], bl[4][2];
            #pragma unroll
            for (int mi = 0; mi < 4; mi++) {
                int r = wm + mi * 16 + g;
                spl(As[p][r    ][kk + t4],     ah[mi][0], al[mi][0]);
                spl(As[p][r + 8][kk + t4],     ah[mi][1], al[mi][1]);
                spl(As[p][r    ][kk + t4 + 4], ah[mi][2], al[mi][2]);
                spl(As[p][r + 8][kk + t4 + 4], ah[mi][3], al[mi][3]);
            }
            #pragma unroll
            for (int ni = 0; ni < 4; ni++) {
                int r = wn + ni * 8 + g;
                spl(Bs[p][r][kk + t4],     bh[ni][0], bl[ni][0]);
                spl(Bs[p][r][kk + t4 + 4], bh[ni][1], bl[ni][1]);
            }
            #pragma unroll
            for (int mi = 0; mi < 4; mi++)
                #pragma unroll
                for (int ni = 0; ni < 4; ni++) {
                    float* cc = c[mi][ni];
                    MMA_TF32(cc, ah[mi][0], ah[mi][1], ah[mi][2], ah[mi][3],
                                 bl[ni][0], bl[ni][1]);
                    MMA_TF32(cc, al[mi][0], al[mi][1], al[mi][2], al[mi][3],
                                 bh[ni][0], bh[ni][1]);
                    MMA_TF32(cc, ah[mi][0], ah[mi][1], ah[mi][2], ah[mi][3],
                                 bh[ni][0], bh[ni][1]);
                }
        }
        if (t + 1 < T) {
            asm volatile("cp.async.wait_group 0;" ::: "memory");
            __syncthreads();
            p ^= 1;
        }
    }
    #undef LOAD_TILE

    // ---- normal epilogue ----
    #pragma unroll
    for (int mi = 0; mi < 4; mi++) {
        int r0 = m0 + wm + mi * 16 + g;
        int r1 = r0 + 8;
        float xm0 = 0.f, xm1 = 0.f;
        if (mode == 1) { xm0 = xb[r0]; xm1 = xb[r1]; }
        #pragma unroll
        for (int ni = 0; ni < 4; ni++) {
            int n = n0 + wn + ni * 8 + t4 * 2;
            if (n < N) {
                float v0 = c[mi][ni][0], v1 = c[mi][ni][1];
                float v2 = c[mi][ni][2], v3 = c[mi][ni][3];
                if (mode == 1) {
                    float xn0 = xb[n], xn1 = xb[n + 1];
                    v0 = 2.f * v0 - xm0 - xn0;  v1 = 2.f * v1 - xm0 - xn1;
                    v2 = 2.f * v2 - xm1 - xn0;  v3 = 2.f * v3 - xm1 - xn1;
                } else if (mode == 2) {
                    float s0 = gg[n] * BN_SCALE, s1 = gg[n + 1] * BN_SCALE;
                    float b0v = bb[n], b1v = bb[n + 1];
                    v0 = fmaf(s0, v0, b0v); v0 = (v0 > 0.f) ? v0 : expm1f(v0);
                    v1 = fmaf(s1, v1, b1v); v1 = (v1 > 0.f) ? v1 : expm1f(v1);
                    v2 = fmaf(s0, v2, b0v); v2 = (v2 > 0.f) ? v2 : expm1f(v2);
                    v3 = fmaf(s1, v3, b1v); v3 = (v3 > 0.f) ? v3 : expm1f(v3);
                }
                float2 p0 = {v0, v1}, p1 = {v2, v3};
                *(float2*)&C[(size_t)r0 * ldc + n] = p0;
                *(float2*)&C[(size_t)r1 * ldc + n] = p1;
            }
        }
    }

    // ---- mirror epilogue (sym, strictly lower blocks): C[n][m] via smem transpose ----
    // stride 132 floats = 528B (multiple of 16B) keeps float4 accesses aligned.
    if (sym && blockIdx.x < blockIdx.y) {
        float (*st)[132] = reinterpret_cast<float(*)[132]>(&As[0][0][0]); // 32x132x4 = 16.9KB
        #pragma unroll 1
        for (int s = 0; s < 4; s++) {    // s = ni strip; covers 32 mirror rows
            __syncthreads();
            #pragma unroll
            for (int mi = 0; mi < 4; mi++) {
                int r0l = wm + mi * 16 + g;       // local row 0..127
                int r0 = m0 + r0l, r1 = r0 + 8;
                int n  = n0 + wn + s * 8 + t4 * 2;
                float xm0 = xb[r0], xm1 = xb[r1];
                float xn0 = xb[n],  xn1 = xb[n + 1];
                float v0 = 2.f * c[mi][s][0] - xm0 - xn0;
                float v1 = 2.f * c[mi][s][1] - xm0 - xn1;
                float v2 = 2.f * c[mi][s][2] - xm1 - xn0;
                float v3 = 2.f * c[mi][s][3] - xm1 - xn1;
                int cl = (w >> 1) * 8 + t4 * 2;   // strip-local col 0..31
                st[cl    ][r0l]     = v0;
                st[cl + 1][r0l]     = v1;
                st[cl    ][r0l + 8] = v2;
                st[cl + 1][r0l + 8] = v3;
            }
            __syncthreads();
            int rsel = tid >> 3;                   // 0..31
            int wnq = rsel >> 3, off = rsel & 7;
            int nl = wnq * 32 + s * 8 + off;       // tile-local col = mirror row
            int colm = (tid & 7) * 16;
            float* dst = &C[(size_t)(n0 + nl) * ldc + m0 + colm];
            const float* src = &st[rsel][colm];
            #pragma unroll
            for (int q = 0; q < 4; q++)
                *(float4*)(dst + q * 4) = *(const float4*)(src + q * 4);
        }
    }
}

// ---------------- top-k (k=20): u64 keys, cached top-3 tournament ----------------
// key = ordered(val)<<32 | (1023-idx): larger key = larger val, ties -> lower idx.
__global__ void __launch_bounds__(256) topk_kernel(
        const float* __restrict__ D, int* __restrict__ out) {
    int warp = (blockIdx.x * blockDim.x + threadIdx.x) >> 5;
    int lane = threadIdx.x & 31;
    const float* row = D + (size_t)warp * NP;
    unsigned long long k[32];
    #pragma unroll
    for (int j = 0; j < 32; j++) {
        int idx = lane + j * 32;
        unsigned u = __float_as_uint(row[idx]);
        unsigned o = (u & 0x80000000u) ? ~u : (u | 0x80000000u);
        k[j] = ((unsigned long long)o << 32) | (unsigned)(1023 - idx);
    }
    int base = warp & ~(NP - 1);   // batch base as global row
    unsigned long long s0 = 0, s1 = 0, s2 = 0;
    // initial top-3
    #pragma unroll
    for (int j = 0; j < 32; j++) {
        unsigned long long x = k[j];
        if (x > s0)      { s2 = s1; s1 = s0; s0 = x; }
        else if (x > s1) { s2 = s1; s1 = x; }
        else if (x > s2) { s2 = x; }
    }
    for (int it = 0; it < KNN; it++) {
        unsigned long long wv = s0;
        #pragma unroll
        for (int off = 16; off; off >>= 1) {
            unsigned long long o = __shfl_xor_sync(0xffffffffu, wv, off);
            if (o > wv) wv = o;
        }
        if (s0 == wv) {          // unique winner pops
            s0 = s1; s1 = s2; s2 = 0;
            if (s0 == 0) {       // cache exhausted: refill top-3 among keys < wv
                #pragma unroll
                for (int j = 0; j < 32; j++) {
                    unsigned long long x = k[j];
                    if (x < wv) {
                        if (x > s0)      { s2 = s1; s1 = s0; s0 = x; }
                        else if (x > s1) { s2 = s1; s1 = x; }
                        else if (x > s2) { s2 = x; }
                    }
                }
            }
        }
        if (lane == 0) out[warp * KNN + it] = base + 1023 - (int)(wv & 1023u);
    }
}

// ---------------- edge-conv aggregation (+ fused rowsum for next layer) ----------------
__global__ void __launch_bounds__(256) aggregate_kernel(
        const float* __restrict__ Yn, const float* __restrict__ Yc,
        int C, const int* __restrict__ idx,
        const float* __restrict__ gg, const float* __restrict__ bb,
        float* __restrict__ outp /* = g_cat + off, ld 512 */,
        float* __restrict__ xxout) {
    int r = blockIdx.x;
    int c = threadIdx.x;
    __shared__ int sidx[KNN];
    __shared__ float red[256];
    if (c < KNN) sidx[c] = idx[r * KNN + c];
    __syncthreads();
    float vmax = -INFINITY, vmin = INFINITY;
    #pragma unroll 4
    for (int j = 0; j < KNN; j++) {
        float v = Yn[(size_t)sidx[j] * C + c];
        vmax = fmaxf(vmax, v);
        vmin = fminf(vmin, v);
    }
    float center = Yc[(size_t)r * C + c] - Yn[(size_t)r * C + c];
    float s = gg[c] * BN_SCALE;
    float h = s * ((s >= 0.f ? vmax : vmin) + center) + bb[c];
    float e = (h > 0.f) ? h : expm1f(h);
    outp[(size_t)r * 512 + c] = e;
    if (xxout) {
        red[c] = e * e;
        __syncthreads();
        for (int st = blockDim.x >> 1; st > 0; st >>= 1) {
            if (c < st) red[c] += red[c + st];
            __syncthreads();
        }
        if (c == 0) xxout[r] = red[0];
    }
}

// ---------------- global max/mean pooling ----------------
__global__ void __launch_bounds__(256) pool_partial(
        const float* __restrict__ h,
        float* __restrict__ pmax, float* __restrict__ psum) {
    int o  = blockIdx.y * 256 + threadIdx.x;
    int b  = blockIdx.x;
    int nz = blockIdx.z;
    float m = -INFINITY, s = 0.f;
    for (int n = nz * 64; n < nz * 64 + 64; n++) {
        float v = h[((size_t)(b * NP + n)) * 1024 + o];
        m = fmaxf(m, v); s += v;
    }
    pmax[(nz * NB + b) * 1024 + o] = m;
    psum[(nz * NB + b) * 1024 + o] = s;
}

__global__ void __launch_bounds__(256) pool_combine(
        const float* __restrict__ pmax, const float* __restrict__ psum,
        float* __restrict__ f) {
    int t = blockIdx.x * 256 + threadIdx.x;
    if (t >= NB * 1024) return;
    int b = t >> 10, o = t & 1023;
    float m = -INFINITY, s = 0.f;
    for (int c = 0; c < 16; c++) {
        m = fmaxf(m, pmax[(c * NB + b) * 1024 + o]);
        s += psum[(c * NB + b) * 1024 + o];
    }
    f[b * 2048 + o] = m;
    f[b * 2048 + 1024 + o] = s * (1.f / 1024.f);
}

// ---------------- tiny MLP: one warp per output element ----------------
__global__ void __launch_bounds__(256) mlp_kernel(
        const float* __restrict__ in, int Kd,
        const float* __restrict__ W,
        const float* __restrict__ gg, const float* __restrict__ bb,
        float* __restrict__ out, int Nout, int rows, int bnelu) {
    int wid  = (blockIdx.x * blockDim.x + threadIdx.x) >> 5;
    int lane = threadIdx.x & 31;
    if (wid >= rows * Nout) return;
    int r = wid / Nout, o = wid % Nout;
    const float* a = in + (size_t)r * Kd;
    const float* w = W  + (size_t)o * Kd;
    float s = 0.f;
    for (int k = lane; k < Kd; k += 32) s += a[k] * w[k];
    #pragma unroll
    for (int off = 16; off; off >>= 1) s += __shfl_xor_sync(0xffffffffu, s, off);
    if (lane == 0) {
        float v;
        if (bnelu) {
            float sc = gg[o] * BN_SCALE;
            v = fmaf(sc, s, bb[o]);
            v = (v > 0.f) ? v : expm1f(v);
        } else {
            v = s + bb[o];
        }
        out[(size_t)r * Nout + o] = v;
    }
}

extern "C" void kernel_launch(void* const* d_in, const int* in_sizes, int n_in,
                              void* d_out, int out_size) {
    const float* x   = (const float*)d_in[0];
    const float* W1  = (const float*)d_in[1];
    const float* g1  = (const float*)d_in[2];
    const float* b1  = (const float*)d_in[3];
    const float* W2  = (const float*)d_in[4];
    const float* g2  = (const float*)d_in[5];
    const float* b2  = (const float*)d_in[6];
    const float* W3  = (const float*)d_in[7];
    const float* g3  = (const float*)d_in[8];
    const float* b3  = (const float*)d_in[9];
    const float* W4  = (const float*)d_in[10];
    const float* g4  = (const float*)d_in[11];
    const float* b4  = (const float*)d_in[12];
    const float* W5  = (const float*)d_in[13];
    const float* g5  = (const float*)d_in[14];
    const float* b5  = (const float*)d_in[15];
    const float* Wl1 = (const float*)d_in[16];
    const float* gl1 = (const float*)d_in[17];
    const float* bl1 = (const float*)d_in[18];
    const float* Wl2 = (const float*)d_in[19];
    const float* gl2 = (const float*)d_in[20];
    const float* bl2 = (const float*)d_in[21];
    const float* Wl3 = (const float*)d_in[22];
    const float* bl3 = (const float*)d_in[23];

    float *dist, *cat, *Y, *xx, *pmax, *psum, *f, *f1, *f2;
    int* idx;
    cudaGetSymbolAddress((void**)&dist, g_dist);
    cudaGetSymbolAddress((void**)&cat,  g_cat);
    cudaGetSymbolAddress((void**)&Y,    g_Y);
    cudaGetSymbolAddress((void**)&xx,   g_xx);
    cudaGetSymbolAddress((void**)&idx,  g_idx);
    cudaGetSymbolAddress((void**)&pmax, g_pmax);
    cudaGetSymbolAddress((void**)&psum, g_psum);
    cudaGetSymbolAddress((void**)&f,    g_f);
    cudaGetSymbolAddress((void**)&f1,   g_f1);
    cudaGetSymbolAddress((void**)&f2,   g_f2);

    dim3 blk(16, 16);

    // ---------- layer 1 (fp32, K=3) ----------
    rowsum_kernel<<<NR / 256, 256>>>(x, 3, 3, xx);
    gemm_nt<<<dim3(NP / 64, NP / 64, NB), blk>>>(1, x, 3, NP * 3, x, 3, NP * 3,
                                                 dist, NP, NP * NP, 3, xx, NP);
    topk_kernel<<<NR / 8, 256>>>(dist, idx);
    // merged Yn/Yc: z=0 -> Wd, z=1 -> Wc
    gemm_nt<<<dim3(1, NR / 64, 2), blk>>>(0, x, 3, 0, W1, 6, 3,
                                          Y, 64, NR * 64, 3, nullptr, 0);
    aggregate_kernel<<<NR, 64>>>(Y, Y + (size_t)NR * 64, 64, idx, g1, b1, cat + 0, xx);

    // ---------- layers 2-4 (split-tf32) ----------
    struct { const float* X; int Cin; const float* W; const float* g; const float* b;
             int Cout; int off; } L[3] = {
        { cat + 0,   64,  W2, g2, b2,  64,  64 },
        { cat + 64,  64,  W3, g3, b3, 128, 128 },
        { cat + 128, 128, W4, g4, b4, 256, 256 },
    };
    for (int li = 0; li < 3; li++) {
        // symmetric dist (xx from previous aggregate)
        gemm_tf32<<<dim3(NP / 128, NP / 128, NB), 256>>>(1, NP, 1,
            L[li].X, 512, NP * 512, L[li].X, 512, NP * 512,
            dist, NP, NP * NP, L[li].Cin, xx, NP, nullptr, nullptr);
        topk_kernel<<<NR / 8, 256>>>(dist, idx);
        // merged Yn/Yc via z
        gemm_tf32<<<dim3((L[li].Cout + 127) / 128, NR / 128, 2), 256>>>(0, L[li].Cout, 0,
            L[li].X, 512, 0, L[li].W, 2 * L[li].Cin, L[li].Cin,
            Y, L[li].Cout, NR * L[li].Cout, L[li].Cin, nullptr, 0, nullptr, nullptr);
        aggregate_kernel<<<NR, L[li].Cout>>>(Y, Y + (size_t)NR * L[li].Cout,
            L[li].Cout, idx, L[li].g, L[li].b, cat + L[li].off,
            (li < 2) ? xx : nullptr);
    }

    // ---------- conv5: h = elu(bn(cat @ W5^T)), reuse dist as h ----------
    gemm_tf32<<<dim3(1024 / 128, NR / 128, 1), 256>>>(2, 1024, 0,
        cat, 512, 0, W5, 512, 0,
        dist, 1024, 0, 512, nullptr, 0, g5, b5);

    // ---------- pooling + MLP head ----------
    pool_partial<<<dim3(NB, 4, 16), 256>>>(dist, pmax, psum);
    pool_combine<<<32, 256>>>(pmax, psum, f);
    mlp_kernel<<<512, 256>>>(f,  2048, Wl1, gl1, bl1, f1, 512, NB, 1);
    mlp_kernel<<<256, 256>>>(f1, 512,  Wl2, gl2, bl2, f2, 256, NB, 1);
    mlp_kernel<<<40,  256>>>(f2, 256,  Wl3, nullptr, bl3, (float*)d_out, 40, NB, 0);
}